// round 4
// baseline (speedup 1.0000x reference)
#include <cuda_runtime.h>
#include <math.h>

// ---------------- problem constants ----------------
#define Bc   8
#define Lc   4096
#define Dc   1024
#define Hc   16
#define DHc  64
#define Mc   (Bc * Lc)      // 32768 rows
#define FFDc 4096           // FF * D

// ---------------- device scratch (static, allocation-guard safe) ----------------
__device__ float g_xpe[(size_t)Mc * Dc];   // X + pe (residual 0)
__device__ float g_q  [(size_t)Mc * Dc];   // q, later reused as attn@Wo tmp
__device__ float g_k  [(size_t)Mc * Dc];   // k, later reused as ffn out tmp
__device__ float g_v  [(size_t)Mc * Dc];   // v
__device__ float g_ctx[(size_t)Mc * Dc];   // attention context
__device__ float g_x1 [(size_t)Mc * Dc];   // after LN1 (residual 1)
__device__ float g_h  [(size_t)Mc * FFDc]; // FFN hidden (512 MB)

// ---------------- kernel 1: X + pe ----------------
__global__ void add_pe_kernel(const float* __restrict__ X,
                              const float* __restrict__ pe,
                              float* __restrict__ out) {
    size_t i = (size_t)blockIdx.x * blockDim.x + threadIdx.x;
    const size_t n4 = (size_t)Mc * Dc / 4;
    if (i >= n4) return;
    const size_t per = (size_t)Lc * Dc / 4;  // pe repeats per batch
    float4 x = ((const float4*)X)[i];
    float4 p = ((const float4*)pe)[i % per];
    float4 o;
    o.x = x.x + p.x; o.y = x.y + p.y; o.z = x.z + p.z; o.w = x.w + p.w;
    ((float4*)out)[i] = o;
}

// ---------------- kernel 2: SGEMM  C[M,N] = A[M,K] @ W[K,N] + bias (opt ReLU) ----
// 128x128 tile, BK=8, 256 threads, 8x8 per thread.
template <bool RELU>
__global__ __launch_bounds__(256, 2)
void sgemm_bias_kernel(const float* __restrict__ A,
                       const float* __restrict__ W,
                       const float* __restrict__ bias,
                       float* __restrict__ C,
                       int N, int K) {
    const int BM = 128, BN = 128, BK = 8;
    __shared__ float As[BK][BM];   // transposed A tile
    __shared__ float Bs[BK][BN];

    const int tid = threadIdx.x;
    const int tx = tid & 15;       // 0..15 -> N direction (8 cols each)
    const int ty = tid >> 4;       // 0..15 -> M direction (8 rows each)

    const size_t bm = blockIdx.y;
    const size_t bn = blockIdx.x;

    const float* Ab = A + bm * BM * (size_t)K;
    const float* Wb = W + bn * BN;

    float acc[8][8];
#pragma unroll
    for (int i = 0; i < 8; i++) {
#pragma unroll
        for (int j = 0; j < 8; j++) acc[i][j] = 0.f;
    }

    const int arow = tid >> 1;           // 0..127
    const int acol = (tid & 1) * 4;      // 0 or 4
    const int brow = tid >> 5;           // 0..7
    const int bcol = (tid & 31) * 4;     // 0..124

    for (int k0 = 0; k0 < K; k0 += BK) {
        float4 a = *(const float4*)(Ab + (size_t)arow * K + k0 + acol);
        As[acol + 0][arow] = a.x;
        As[acol + 1][arow] = a.y;
        As[acol + 2][arow] = a.z;
        As[acol + 3][arow] = a.w;
        *(float4*)(&Bs[brow][bcol]) =
            *(const float4*)(Wb + (size_t)(k0 + brow) * N + bcol);
        __syncthreads();

#pragma unroll
        for (int kk = 0; kk < BK; kk++) {
            float4 a0 = *(const float4*)(&As[kk][ty * 8]);
            float4 a1 = *(const float4*)(&As[kk][ty * 8 + 4]);
            float4 b0 = *(const float4*)(&Bs[kk][tx * 8]);
            float4 b1 = *(const float4*)(&Bs[kk][tx * 8 + 4]);
            float ra[8] = {a0.x, a0.y, a0.z, a0.w, a1.x, a1.y, a1.z, a1.w};
            float rb[8] = {b0.x, b0.y, b0.z, b0.w, b1.x, b1.y, b1.z, b1.w};
#pragma unroll
            for (int i = 0; i < 8; i++) {
#pragma unroll
                for (int j = 0; j < 8; j++)
                    acc[i][j] = fmaf(ra[i], rb[j], acc[i][j]);
            }
        }
        __syncthreads();
    }

    const size_t crow0 = bm * BM + ty * 8;
    const int    ccol0 = (int)(bn * BN) + tx * 8;
    float bs0[8];
#pragma unroll
    for (int j = 0; j < 8; j++) bs0[j] = bias[ccol0 + j];

#pragma unroll
    for (int i = 0; i < 8; i++) {
        float v[8];
#pragma unroll
        for (int j = 0; j < 8; j++) {
            float t = acc[i][j] + bs0[j];
            if (RELU) t = fmaxf(t, 0.f);
            v[j] = t;
        }
        float* cp = C + (crow0 + i) * (size_t)N + ccol0;
        *(float4*)cp       = make_float4(v[0], v[1], v[2], v[3]);
        *(float4*)(cp + 4) = make_float4(v[4], v[5], v[6], v[7]);
    }
}

// ---------------- kernel 3: window-3 local attention ----------------
// One warp per (b, l, h). Lane j handles dims {j, j+32} of DH=64.
__global__ void attn_kernel(const float* __restrict__ q,
                            const float* __restrict__ k,
                            const float* __restrict__ v,
                            const unsigned char* __restrict__ mask,
                            float* __restrict__ ctx) {
    int gw   = (int)((blockIdx.x * (size_t)blockDim.x + threadIdx.x) >> 5);
    int lane = threadIdx.x & 31;
    if (gw >= Mc * Hc) return;

    int h  = gw & (Hc - 1);
    int bl = gw >> 4;            // Hc = 16
    int l  = bl & (Lc - 1);
    int b  = bl >> 12;           // Lc = 4096

    const float* qp = q + (size_t)bl * Dc + h * DHc;
    float q0 = qp[lane], q1 = qp[lane + 32];

    float s[3];
#pragma unroll
    for (int w = 0; w < 3; w++) {
        int idx    = l - 1 + w;
        bool valid = (idx >= 0) && (idx < Lc);
        int idxc   = min(max(idx, 0), Lc - 1);
        const float* kp = k + ((size_t)(b * Lc + idxc)) * Dc + h * DHc;
        float p = q0 * kp[lane] + q1 * kp[lane + 32];
#pragma unroll
        for (int off = 16; off > 0; off >>= 1)
            p += __shfl_xor_sync(0xffffffffu, p, off);
        bool ok = valid && (mask[b * Lc + idxc] == 0);
        s[w] = ok ? p * 0.125f : -1e30f;   // 1/sqrt(64)
    }

    float m  = fmaxf(s[0], fmaxf(s[1], s[2]));
    float e0 = expf(s[0] - m), e1 = expf(s[1] - m), e2 = expf(s[2] - m);
    float inv = 1.0f / (e0 + e1 + e2);
    float a0 = e0 * inv, a1 = e1 * inv, a2 = e2 * inv;

    int i0 = max(l - 1, 0), i2 = min(l + 1, Lc - 1);
    const float* v0 = v + ((size_t)(b * Lc + i0)) * Dc + h * DHc;
    const float* v1 = v + ((size_t)(b * Lc + l )) * Dc + h * DHc;
    const float* v2 = v + ((size_t)(b * Lc + i2)) * Dc + h * DHc;

    float o0 = a0 * v0[lane]      + a1 * v1[lane]      + a2 * v2[lane];
    float o1 = a0 * v0[lane + 32] + a1 * v1[lane + 32] + a2 * v2[lane + 32];

    float* cp = ctx + (size_t)bl * Dc + h * DHc;
    cp[lane]      = o0;
    cp[lane + 32] = o1;
}

// ---------------- kernel 4: out = LayerNorm(a + b) * gamma + beta ------------
__device__ __forceinline__ float block_reduce_sum(float val, float* red) {
    int lane = threadIdx.x & 31, warp = threadIdx.x >> 5;
#pragma unroll
    for (int o = 16; o > 0; o >>= 1) val += __shfl_xor_sync(0xffffffffu, val, o);
    if (lane == 0) red[warp] = val;
    __syncthreads();
    if (warp == 0) {
        float t = (lane < 8) ? red[lane] : 0.f;   // 256 threads -> 8 warps
#pragma unroll
        for (int o = 4; o > 0; o >>= 1) t += __shfl_xor_sync(0xffffffffu, t, o);
        if (lane == 0) red[0] = t;
    }
    __syncthreads();
    float r = red[0];
    __syncthreads();
    return r;
}

__global__ void add_ln_kernel(const float* __restrict__ a,
                              const float* __restrict__ b,
                              const float* __restrict__ gamma,
                              const float* __restrict__ beta,
                              float* __restrict__ out) {
    __shared__ float red[32];
    const size_t row = blockIdx.x;
    const int tid = threadIdx.x;  // 256 threads, 4 floats each (D=1024)

    float4 x = ((const float4*)(a + row * Dc))[tid];
    float4 y = ((const float4*)(b + row * Dc))[tid];
    float v0 = x.x + y.x, v1 = x.y + y.y, v2 = x.z + y.z, v3 = x.w + y.w;

    float mean = block_reduce_sum(v0 + v1 + v2 + v3, red) * (1.0f / Dc);
    float d0 = v0 - mean, d1 = v1 - mean, d2 = v2 - mean, d3 = v3 - mean;
    float var = block_reduce_sum(d0 * d0 + d1 * d1 + d2 * d2 + d3 * d3, red) *
                (1.0f / Dc);
    float rstd = rsqrtf(var + 1e-5f);

    float4 g = ((const float4*)gamma)[tid];
    float4 be = ((const float4*)beta)[tid];
    float4 o;
    o.x = d0 * rstd * g.x + be.x;
    o.y = d1 * rstd * g.y + be.y;
    o.z = d2 * rstd * g.z + be.z;
    o.w = d3 * rstd * g.w + be.w;
    ((float4*)(out + row * Dc))[tid] = o;
}

// ---------------- launch ----------------
extern "C" void kernel_launch(void* const* d_in, const int* in_sizes, int n_in,
                              void* d_out, int out_size) {
    (void)in_sizes; (void)n_in; (void)out_size;
    const float*         X    = (const float*)d_in[0];
    const unsigned char* mask = (const unsigned char*)d_in[1];
    const float* pe  = (const float*)d_in[2];
    const float* Wq  = (const float*)d_in[3];
    const float* Wk  = (const float*)d_in[4];
    const float* Wv  = (const float*)d_in[5];
    const float* bq  = (const float*)d_in[6];
    const float* bk  = (const float*)d_in[7];
    const float* bv  = (const float*)d_in[8];
    const float* Wo  = (const float*)d_in[9];
    const float* bo  = (const float*)d_in[10];
    const float* g1  = (const float*)d_in[11];
    const float* be1 = (const float*)d_in[12];
    const float* W1  = (const float*)d_in[13];
    const float* b1  = (const float*)d_in[14];
    const float* W2  = (const float*)d_in[15];
    const float* b2  = (const float*)d_in[16];
    const float* g2  = (const float*)d_in[17];
    const float* be2 = (const float*)d_in[18];
    float* out = (float*)d_out;

    float *xpe, *q, *k, *v, *ctx, *x1, *hbuf;
    cudaGetSymbolAddress((void**)&xpe,  g_xpe);
    cudaGetSymbolAddress((void**)&q,    g_q);
    cudaGetSymbolAddress((void**)&k,    g_k);
    cudaGetSymbolAddress((void**)&v,    g_v);
    cudaGetSymbolAddress((void**)&ctx,  g_ctx);
    cudaGetSymbolAddress((void**)&x1,   g_x1);
    cudaGetSymbolAddress((void**)&hbuf, g_h);

    // 1. X + pe
    add_pe_kernel<<<(Mc * Dc / 4 + 255) / 256, 256>>>(X, pe, xpe);

    // 2. QKV projections
    dim3 gD(Dc / 128, Mc / 128);      // (8, 256)
    sgemm_bias_kernel<false><<<gD, 256>>>(xpe, Wq, bq, q, Dc, Dc);
    sgemm_bias_kernel<false><<<gD, 256>>>(xpe, Wk, bk, k, Dc, Dc);
    sgemm_bias_kernel<false><<<gD, 256>>>(xpe, Wv, bv, v, Dc, Dc);

    // 3. window-3 attention
    attn_kernel<<<(Mc * Hc) / 8, 256>>>(q, k, v, mask, ctx);

    // 4. output projection (reuse q as tmp)
    sgemm_bias_kernel<false><<<gD, 256>>>(ctx, Wo, bo, q, Dc, Dc);

    // 5. LN1(xpe + attn_proj)
    add_ln_kernel<<<Mc, 256>>>(xpe, q, g1, be1, x1);

    // 6. FFN
    dim3 gF(FFDc / 128, Mc / 128);    // (32, 256)
    sgemm_bias_kernel<true ><<<gF, 256>>>(x1, W1, b1, hbuf, FFDc, Dc);
    sgemm_bias_kernel<false><<<gD, 256>>>(hbuf, W2, b2, k /*tmp*/, Dc, FFDc);

    // 7. LN2(x1 + ffn) -> output
    add_ln_kernel<<<Mc, 256>>>(x1, k, g2, be2, out);
}

// round 7
// speedup vs baseline: 2.8394x; 2.8394x over previous
#include <cuda_runtime.h>
#include <math.h>
#include <stdint.h>

// ---------------- problem constants ----------------
#define Bc   8
#define Lc   4096
#define Dc   1024
#define Hc   16
#define DHc  64
#define Mc   (Bc * Lc)      // 32768 rows
#define FFDc 4096           // FF * D

// ---------------- device scratch (static, allocation-guard safe) ----------------
__device__ float g_xpe[(size_t)Mc * Dc];   // X + pe (residual 0)
__device__ float g_q  [(size_t)Mc * Dc];   // q, later reused as attn@Wo tmp
__device__ float g_k  [(size_t)Mc * Dc];   // k, later reused as ffn out tmp
__device__ float g_v  [(size_t)Mc * Dc];   // v
__device__ float g_ctx[(size_t)Mc * Dc];   // attention context
__device__ float g_x1 [(size_t)Mc * Dc];   // after LN1 (residual 1)
__device__ float g_h  [(size_t)Mc * FFDc]; // FFN hidden
// transposed + tf32-rounded weights ([N, K] row-major)
__device__ float g_wqT[(size_t)Dc * Dc];
__device__ float g_wkT[(size_t)Dc * Dc];
__device__ float g_wvT[(size_t)Dc * Dc];
__device__ float g_woT[(size_t)Dc * Dc];
__device__ float g_w1T[(size_t)Dc * FFDc];
__device__ float g_w2T[(size_t)FFDc * Dc];

// ---------------- small PTX helpers ----------------
__device__ __forceinline__ uint32_t smem_u32(const void* p) {
    uint32_t a;
    asm("{ .reg .u64 t; cvta.to.shared.u64 t, %1; cvt.u32.u64 %0, t; }"
        : "=r"(a) : "l"(p));
    return a;
}

__device__ __forceinline__ uint32_t cvt_tf32(float x) {
    uint32_t r;
    asm("cvt.rna.tf32.f32 %0, %1;" : "=r"(r) : "f"(x));
    return r;
}

__device__ __forceinline__ void cp_async16(uint32_t dst, const void* src) {
    asm volatile("cp.async.cg.shared.global [%0], [%1], 16;"
                 :: "r"(dst), "l"(src));
}

__device__ __forceinline__ void mma_tf32(float* c, const uint32_t* a,
                                         const uint32_t* b) {
    asm volatile(
        "mma.sync.aligned.m16n8k8.row.col.f32.tf32.tf32.f32 "
        "{%0,%1,%2,%3}, {%4,%5,%6,%7}, {%8,%9}, {%0,%1,%2,%3};"
        : "+f"(c[0]), "+f"(c[1]), "+f"(c[2]), "+f"(c[3])
        : "r"(a[0]), "r"(a[1]), "r"(a[2]), "r"(a[3]),
          "r"(b[0]), "r"(b[1]));
}

// ---------------- kernel 1: X + pe ----------------
__global__ void add_pe_kernel(const float* __restrict__ X,
                              const float* __restrict__ pe,
                              float* __restrict__ out) {
    size_t i = (size_t)blockIdx.x * blockDim.x + threadIdx.x;
    const size_t n4 = (size_t)Mc * Dc / 4;
    if (i >= n4) return;
    const size_t per = (size_t)Lc * Dc / 4;
    float4 x = ((const float4*)X)[i];
    float4 p = ((const float4*)pe)[i % per];
    float4 o;
    o.x = x.x + p.x; o.y = x.y + p.y; o.z = x.z + p.z; o.w = x.w + p.w;
    ((float4*)out)[i] = o;
}

// ---------------- transpose + tf32-round: out[C,R] = rna(in[R,C]^T) ----------
__global__ void transpose_kernel(const float* __restrict__ in,
                                 float* __restrict__ out, int R, int C) {
    __shared__ float t[32][33];
    int bx = blockIdx.x * 32;
    int by = blockIdx.y * 32;
    int x = threadIdx.x, y = threadIdx.y;  // 32 x 8
#pragma unroll
    for (int i = 0; i < 32; i += 8)
        t[y + i][x] = in[(size_t)(by + y + i) * C + bx + x];
    __syncthreads();
#pragma unroll
    for (int i = 0; i < 32; i += 8)
        out[(size_t)(bx + y + i) * R + by + x] =
            __uint_as_float(cvt_tf32(t[x][y + i]));
}

// ============================================================================
// tf32 mma.sync GEMM:  C[M,N] = A[M,K] @ Wt[N,K]^T + bias  (optional ReLU)
// 128x128 tile, BK=32, 3-stage cp.async pipeline, 8 warps (2x4), 64x32/warp.
// smem row stride = 36 floats: conflict-free fragment LDS + 16B cp.async align.
// ============================================================================
#define BKt      32
#define SROW     36
#define HALF_F   (128 * SROW)          // floats per A (or B) tile
#define STAGE_F  (2 * HALF_F)          // A + B
#define NST      3
#define GEMM_SMEM (NST * STAGE_F * 4)  // 110592 bytes

template <bool RELU>
__global__ __launch_bounds__(256, 1)
void mma_gemm_kernel(const float* __restrict__ A,
                     const float* __restrict__ Wt,   // [N, K] row-major, tf32
                     const float* __restrict__ bias,
                     float* __restrict__ C,
                     int N, int K) {
    extern __shared__ float sm[];
    const int tid  = threadIdx.x;
    const int wid  = tid >> 5, lane = tid & 31;
    const int g    = lane >> 2, t = lane & 3;
    const int wm   = wid >> 2, wn = wid & 3;       // 2 x 4 warp grid
    const size_t m0 = (size_t)blockIdx.y * 128;
    const size_t n0 = (size_t)blockIdx.x * 128;
    const float* gA = A  + m0 * (size_t)K;
    const float* gB = Wt + n0 * (size_t)K;
    const uint32_t sbase = smem_u32(sm);

    float acc[4][4][4];
#pragma unroll
    for (int i = 0; i < 4; i++)
#pragma unroll
        for (int j = 0; j < 4; j++)
#pragma unroll
            for (int r = 0; r < 4; r++) acc[i][j][r] = 0.f;

    const int nch = K / BKt;

    // per-thread tile-load mapping: 4 x 16B chunks for A, 4 for B
    auto load_stage = [&](int c, int slot) {
        uint32_t sA = sbase + (uint32_t)slot * STAGE_F * 4;
        uint32_t sB = sA + HALF_F * 4;
        const float* a = gA + (size_t)c * BKt;
        const float* b = gB + (size_t)c * BKt;
#pragma unroll
        for (int qq = 0; qq < 4; qq++) {
            int id = qq * 256 + tid;
            int r = id >> 3, c16 = id & 7;
            uint32_t so = (uint32_t)(r * SROW + c16 * 4) * 4;
            cp_async16(sA + so, a + (size_t)r * K + c16 * 4);
            cp_async16(sB + so, b + (size_t)r * K + c16 * 4);
        }
        asm volatile("cp.async.commit_group;" ::: "memory");
    };

    load_stage(0, 0);
    load_stage(1, 1);

    for (int c = 0; c < nch; c++) {
        int slot = c % NST;
        asm volatile("cp.async.wait_group 1;" ::: "memory");
        __syncthreads();
        if (c + 2 < nch) load_stage(c + 2, (c + 2) % NST);

        const float* As = sm + slot * STAGE_F;
        const float* Bs = As + HALF_F;

#pragma unroll
        for (int ks = 0; ks < 4; ks++) {
            const int kk = ks * 8;
            uint32_t af[4][4], bf[4][2];
#pragma unroll
            for (int mt = 0; mt < 4; mt++) {
                const float* p = As + (wm * 64 + mt * 16 + g) * SROW + kk + t;
                af[mt][0] = cvt_tf32(p[0]);
                af[mt][1] = cvt_tf32(p[8 * SROW]);
                af[mt][2] = cvt_tf32(p[4]);
                af[mt][3] = cvt_tf32(p[8 * SROW + 4]);
            }
#pragma unroll
            for (int nt = 0; nt < 4; nt++) {
                const float* p = Bs + (wn * 32 + nt * 8 + g) * SROW + kk + t;
                bf[nt][0] = __float_as_uint(p[0]);
                bf[nt][1] = __float_as_uint(p[4]);
            }
#pragma unroll
            for (int mt = 0; mt < 4; mt++)
#pragma unroll
                for (int nt = 0; nt < 4; nt++)
                    mma_tf32(acc[mt][nt], af[mt], bf[nt]);
        }
    }

    // epilogue: +bias (+ReLU), float2 stores
#pragma unroll
    for (int mt = 0; mt < 4; mt++) {
        size_t row0 = m0 + wm * 64 + mt * 16 + g;
#pragma unroll
        for (int nt = 0; nt < 4; nt++) {
            int col = (int)n0 + wn * 32 + nt * 8 + t * 2;
            float b0 = bias[col], b1 = bias[col + 1];
            float v0 = acc[mt][nt][0] + b0;
            float v1 = acc[mt][nt][1] + b1;
            float v2 = acc[mt][nt][2] + b0;
            float v3 = acc[mt][nt][3] + b1;
            if (RELU) {
                v0 = fmaxf(v0, 0.f); v1 = fmaxf(v1, 0.f);
                v2 = fmaxf(v2, 0.f); v3 = fmaxf(v3, 0.f);
            }
            *(float2*)(C + row0 * (size_t)N + col)       = make_float2(v0, v1);
            *(float2*)(C + (row0 + 8) * (size_t)N + col) = make_float2(v2, v3);
        }
    }
}

// ---------------- window-3 local attention ----------------
__global__ void attn_kernel(const float* __restrict__ q,
                            const float* __restrict__ k,
                            const float* __restrict__ v,
                            const unsigned char* __restrict__ mask,
                            float* __restrict__ ctx) {
    int gw   = (int)((blockIdx.x * (size_t)blockDim.x + threadIdx.x) >> 5);
    int lane = threadIdx.x & 31;
    if (gw >= Mc * Hc) return;

    int h  = gw & (Hc - 1);
    int bl = gw >> 4;
    int l  = bl & (Lc - 1);
    int b  = bl >> 12;

    const float* qp = q + (size_t)bl * Dc + h * DHc;
    float q0 = qp[lane], q1 = qp[lane + 32];

    float s[3];
#pragma unroll
    for (int w = 0; w < 3; w++) {
        int idx    = l - 1 + w;
        bool valid = (idx >= 0) && (idx < Lc);
        int idxc   = min(max(idx, 0), Lc - 1);
        const float* kp = k + ((size_t)(b * Lc + idxc)) * Dc + h * DHc;
        float p = q0 * kp[lane] + q1 * kp[lane + 32];
#pragma unroll
        for (int off = 16; off > 0; off >>= 1)
            p += __shfl_xor_sync(0xffffffffu, p, off);
        bool ok = valid && (mask[b * Lc + idxc] == 0);
        s[w] = ok ? p * 0.125f : -1e30f;
    }

    float m  = fmaxf(s[0], fmaxf(s[1], s[2]));
    float e0 = expf(s[0] - m), e1 = expf(s[1] - m), e2 = expf(s[2] - m);
    float inv = 1.0f / (e0 + e1 + e2);
    float a0 = e0 * inv, a1 = e1 * inv, a2 = e2 * inv;

    int i0 = max(l - 1, 0), i2 = min(l + 1, Lc - 1);
    const float* v0 = v + ((size_t)(b * Lc + i0)) * Dc + h * DHc;
    const float* v1 = v + ((size_t)(b * Lc + l )) * Dc + h * DHc;
    const float* v2 = v + ((size_t)(b * Lc + i2)) * Dc + h * DHc;

    float o0 = a0 * v0[lane]      + a1 * v1[lane]      + a2 * v2[lane];
    float o1 = a0 * v0[lane + 32] + a1 * v1[lane + 32] + a2 * v2[lane + 32];

    float* cp = ctx + (size_t)bl * Dc + h * DHc;
    cp[lane]      = o0;
    cp[lane + 32] = o1;
}

// ---------------- out = LayerNorm(a + b) * gamma + beta ----------------
__device__ __forceinline__ float block_reduce_sum(float val, float* red) {
    int lane = threadIdx.x & 31, warp = threadIdx.x >> 5;
#pragma unroll
    for (int o = 16; o > 0; o >>= 1) val += __shfl_xor_sync(0xffffffffu, val, o);
    if (lane == 0) red[warp] = val;
    __syncthreads();
    if (warp == 0) {
        float t = (lane < 8) ? red[lane] : 0.f;
#pragma unroll
        for (int o = 4; o > 0; o >>= 1) t += __shfl_xor_sync(0xffffffffu, t, o);
        if (lane == 0) red[0] = t;
    }
    __syncthreads();
    float r = red[0];
    __syncthreads();
    return r;
}

__global__ void add_ln_kernel(const float* __restrict__ a,
                              const float* __restrict__ b,
                              const float* __restrict__ gamma,
                              const float* __restrict__ beta,
                              float* __restrict__ out) {
    __shared__ float red[32];
    const size_t row = blockIdx.x;
    const int tid = threadIdx.x;

    float4 x = ((const float4*)(a + row * Dc))[tid];
    float4 y = ((const float4*)(b + row * Dc))[tid];
    float v0 = x.x + y.x, v1 = x.y + y.y, v2 = x.z + y.z, v3 = x.w + y.w;

    float mean = block_reduce_sum(v0 + v1 + v2 + v3, red) * (1.0f / Dc);
    float d0 = v0 - mean, d1 = v1 - mean, d2 = v2 - mean, d3 = v3 - mean;
    float var = block_reduce_sum(d0 * d0 + d1 * d1 + d2 * d2 + d3 * d3, red) *
                (1.0f / Dc);
    float rstd = rsqrtf(var + 1e-5f);

    float4 g = ((const float4*)gamma)[tid];
    float4 be = ((const float4*)beta)[tid];
    float4 o;
    o.x = d0 * rstd * g.x + be.x;
    o.y = d1 * rstd * g.y + be.y;
    o.z = d2 * rstd * g.z + be.z;
    o.w = d3 * rstd * g.w + be.w;
    ((float4*)(out + row * Dc))[tid] = o;
}

// ---------------- launch ----------------
extern "C" void kernel_launch(void* const* d_in, const int* in_sizes, int n_in,
                              void* d_out, int out_size) {
    (void)in_sizes; (void)n_in; (void)out_size;
    const float*         X    = (const float*)d_in[0];
    const unsigned char* mask = (const unsigned char*)d_in[1];
    const float* pe  = (const float*)d_in[2];
    const float* Wq  = (const float*)d_in[3];
    const float* Wk  = (const float*)d_in[4];
    const float* Wv  = (const float*)d_in[5];
    const float* bq  = (const float*)d_in[6];
    const float* bk  = (const float*)d_in[7];
    const float* bv  = (const float*)d_in[8];
    const float* Wo  = (const float*)d_in[9];
    const float* bo  = (const float*)d_in[10];
    const float* g1  = (const float*)d_in[11];
    const float* be1 = (const float*)d_in[12];
    const float* W1  = (const float*)d_in[13];
    const float* b1  = (const float*)d_in[14];
    const float* W2  = (const float*)d_in[15];
    const float* b2  = (const float*)d_in[16];
    const float* g2  = (const float*)d_in[17];
    const float* be2 = (const float*)d_in[18];
    float* out = (float*)d_out;

    float *xpe, *q, *k, *v, *ctx, *x1, *hbuf;
    float *wqT, *wkT, *wvT, *woT, *w1T, *w2T;
    cudaGetSymbolAddress((void**)&xpe,  g_xpe);
    cudaGetSymbolAddress((void**)&q,    g_q);
    cudaGetSymbolAddress((void**)&k,    g_k);
    cudaGetSymbolAddress((void**)&v,    g_v);
    cudaGetSymbolAddress((void**)&ctx,  g_ctx);
    cudaGetSymbolAddress((void**)&x1,   g_x1);
    cudaGetSymbolAddress((void**)&hbuf, g_h);
    cudaGetSymbolAddress((void**)&wqT,  g_wqT);
    cudaGetSymbolAddress((void**)&wkT,  g_wkT);
    cudaGetSymbolAddress((void**)&wvT,  g_wvT);
    cudaGetSymbolAddress((void**)&woT,  g_woT);
    cudaGetSymbolAddress((void**)&w1T,  g_w1T);
    cudaGetSymbolAddress((void**)&w2T,  g_w2T);

    cudaFuncSetAttribute(mma_gemm_kernel<false>,
                         cudaFuncAttributeMaxDynamicSharedMemorySize, GEMM_SMEM);
    cudaFuncSetAttribute(mma_gemm_kernel<true>,
                         cudaFuncAttributeMaxDynamicSharedMemorySize, GEMM_SMEM);

    // 0. transpose + tf32-round weights ([N,K] row-major)
    dim3 tb(32, 8);
    transpose_kernel<<<dim3(Dc / 32, Dc / 32), tb>>>(Wq, wqT, Dc, Dc);
    transpose_kernel<<<dim3(Dc / 32, Dc / 32), tb>>>(Wk, wkT, Dc, Dc);
    transpose_kernel<<<dim3(Dc / 32, Dc / 32), tb>>>(Wv, wvT, Dc, Dc);
    transpose_kernel<<<dim3(Dc / 32, Dc / 32), tb>>>(Wo, woT, Dc, Dc);
    transpose_kernel<<<dim3(FFDc / 32, Dc / 32), tb>>>(W1, w1T, Dc, FFDc);
    transpose_kernel<<<dim3(Dc / 32, FFDc / 32), tb>>>(W2, w2T, FFDc, Dc);

    // 1. X + pe
    add_pe_kernel<<<(Mc * Dc / 4 + 255) / 256, 256>>>(X, pe, xpe);

    // 2. QKV projections (tensor cores, tf32 mma.sync)
    dim3 gD(Dc / 128, Mc / 128);      // (8, 256)
    mma_gemm_kernel<false><<<gD, 256, GEMM_SMEM>>>(xpe, wqT, bq, q, Dc, Dc);
    mma_gemm_kernel<false><<<gD, 256, GEMM_SMEM>>>(xpe, wkT, bk, k, Dc, Dc);
    mma_gemm_kernel<false><<<gD, 256, GEMM_SMEM>>>(xpe, wvT, bv, v, Dc, Dc);

    // 3. window-3 attention
    attn_kernel<<<(Mc * Hc) / 8, 256>>>(q, k, v, mask, ctx);

    // 4. output projection (reuse q as tmp)
    mma_gemm_kernel<false><<<gD, 256, GEMM_SMEM>>>(ctx, woT, bo, q, Dc, Dc);

    // 5. LN1(xpe + attn_proj)
    add_ln_kernel<<<Mc, 256>>>(xpe, q, g1, be1, x1);

    // 6. FFN
    dim3 gF(FFDc / 128, Mc / 128);    // (32, 256)
    mma_gemm_kernel<true ><<<gF, 256, GEMM_SMEM>>>(x1, w1T, b1, hbuf, FFDc, Dc);
    mma_gemm_kernel<false><<<gD, 256, GEMM_SMEM>>>(hbuf, w2T, b2, k /*tmp*/, Dc, FFDc);

    // 7. LN2(x1 + ffn) -> output
    add_ln_kernel<<<Mc, 256>>>(x1, k, g2, be2, out);
}

// round 8
// speedup vs baseline: 3.4565x; 1.2173x over previous
#include <cuda_runtime.h>
#include <math.h>
#include <stdint.h>

// ---------------- problem constants ----------------
#define Bc   8
#define Lc   4096
#define Dc   1024
#define Hc   16
#define DHc  64
#define Mc   (Bc * Lc)      // 32768 rows
#define FFDc 4096           // FF * D

// ---------------- device scratch (static, allocation-guard safe) ----------------
__device__ float g_xpe[(size_t)Mc * Dc];   // X + pe (residual 0)
__device__ float g_q  [(size_t)Mc * Dc];   // q, later reused as attn@Wo tmp
__device__ float g_k  [(size_t)Mc * Dc];   // k, later reused as ffn out tmp
__device__ float g_v  [(size_t)Mc * Dc];   // v
__device__ float g_ctx[(size_t)Mc * Dc];   // attention context
__device__ float g_x1 [(size_t)Mc * Dc];   // after LN1 (residual 1)
__device__ float g_h  [(size_t)Mc * FFDc]; // FFN hidden
// transposed + tf32-rounded weights ([N, K] row-major)
__device__ float g_wqT[(size_t)Dc * Dc];
__device__ float g_wkT[(size_t)Dc * Dc];
__device__ float g_wvT[(size_t)Dc * Dc];
__device__ float g_woT[(size_t)Dc * Dc];
__device__ float g_w1T[(size_t)Dc * FFDc];
__device__ float g_w2T[(size_t)FFDc * Dc];

// ---------------- small PTX helpers ----------------
__device__ __forceinline__ uint32_t cvt_tf32(float x) {
    uint32_t r;
    asm("cvt.rna.tf32.f32 %0, %1;" : "=r"(r) : "f"(x));
    return r;
}

__device__ __forceinline__ uint32_t smem_u32(const void* p) {
    uint32_t a;
    asm("{ .reg .u64 t; cvta.to.shared.u64 t, %1; cvt.u32.u64 %0, t; }"
        : "=r"(a) : "l"(p));
    return a;
}

__device__ __forceinline__ void cp_async16(uint32_t dst, const void* src) {
    asm volatile("cp.async.cg.shared.global [%0], [%1], 16;"
                 :: "r"(dst), "l"(src));
}

__device__ __forceinline__ void mma_tf32(float* c, const uint32_t* a,
                                         const uint32_t* b) {
    asm volatile(
        "mma.sync.aligned.m16n8k8.row.col.f32.tf32.tf32.f32 "
        "{%0,%1,%2,%3}, {%4,%5,%6,%7}, {%8,%9}, {%0,%1,%2,%3};"
        : "+f"(c[0]), "+f"(c[1]), "+f"(c[2]), "+f"(c[3])
        : "r"(a[0]), "r"(a[1]), "r"(a[2]), "r"(a[3]),
          "r"(b[0]), "r"(b[1]));
}

// ---------------- kernel 1: X + pe ----------------
__global__ void add_pe_kernel(const float* __restrict__ X,
                              const float* __restrict__ pe,
                              float* __restrict__ out) {
    size_t i = (size_t)blockIdx.x * blockDim.x + threadIdx.x;
    const size_t n4 = (size_t)Mc * Dc / 4;
    if (i >= n4) return;
    const size_t per = (size_t)Lc * Dc / 4;
    float4 x = ((const float4*)X)[i];
    float4 p = ((const float4*)pe)[i % per];
    float4 o;
    o.x = x.x + p.x; o.y = x.y + p.y; o.z = x.z + p.z; o.w = x.w + p.w;
    ((float4*)out)[i] = o;
}

// ---------------- transpose + tf32-round: out[C,R] = rna(in[R,C]^T) ----------
__global__ void transpose_kernel(const float* __restrict__ in,
                                 float* __restrict__ out, int R, int C) {
    __shared__ float t[32][33];
    int bx = blockIdx.x * 32;
    int by = blockIdx.y * 32;
    int x = threadIdx.x, y = threadIdx.y;  // 32 x 8
#pragma unroll
    for (int i = 0; i < 32; i += 8)
        t[y + i][x] = in[(size_t)(by + y + i) * C + bx + x];
    __syncthreads();
#pragma unroll
    for (int i = 0; i < 32; i += 8)
        out[(size_t)(bx + y + i) * R + by + x] =
            __uint_as_float(cvt_tf32(t[x][y + i]));
}

// ============================================================================
// tf32 mma.sync GEMM:  C[M,N] = A[M,K] @ Wt[N,K]^T + bias  (optional ReLU)
// 256x128 tile, BK=32, 3-stage cp.async pipeline, 8 warps (4x2), 64x64/warp.
// smem row stride = 36 floats: conflict-free fragment LDS + 16B cp.async align.
// ============================================================================
#define BKt      32
#define SROW     36
#define A_F      (256 * SROW)          // floats in A tile
#define B_F      (128 * SROW)          // floats in B tile
#define STAGE_F  (A_F + B_F)
#define NST      3
#define GEMM_SMEM (NST * STAGE_F * 4)  // 165888 bytes

template <bool RELU>
__global__ __launch_bounds__(256, 1)
void mma_gemm_kernel(const float* __restrict__ A,
                     const float* __restrict__ Wt,   // [N, K] row-major, tf32
                     const float* __restrict__ bias,
                     float* __restrict__ C,
                     int N, int K) {
    extern __shared__ float sm[];
    const int tid  = threadIdx.x;
    const int wid  = tid >> 5, lane = tid & 31;
    const int g    = lane >> 2, t = lane & 3;
    const int wm   = wid >> 1, wn = wid & 1;       // 4 x 2 warp grid
    const size_t m0 = (size_t)blockIdx.y * 256;
    const size_t n0 = (size_t)blockIdx.x * 128;
    const float* gA = A  + m0 * (size_t)K;
    const float* gB = Wt + n0 * (size_t)K;
    const uint32_t sbase = smem_u32(sm);

    float acc[4][8][4];
#pragma unroll
    for (int i = 0; i < 4; i++)
#pragma unroll
        for (int j = 0; j < 8; j++)
#pragma unroll
            for (int r = 0; r < 4; r++) acc[i][j][r] = 0.f;

    const int nch = K / BKt;

    auto load_stage = [&](int c, int slot) {
        uint32_t sA = sbase + (uint32_t)slot * STAGE_F * 4;
        uint32_t sB = sA + A_F * 4;
        const float* a = gA + (size_t)c * BKt;
        const float* b = gB + (size_t)c * BKt;
#pragma unroll
        for (int qq = 0; qq < 8; qq++) {      // A: 256 rows x 8 chunks
            int id = qq * 256 + tid;
            int r = id >> 3, c16 = id & 7;
            uint32_t so = (uint32_t)(r * SROW + c16 * 4) * 4;
            cp_async16(sA + so, a + (size_t)r * K + c16 * 4);
        }
#pragma unroll
        for (int qq = 0; qq < 4; qq++) {      // B: 128 rows x 8 chunks
            int id = qq * 256 + tid;
            int r = id >> 3, c16 = id & 7;
            uint32_t so = (uint32_t)(r * SROW + c16 * 4) * 4;
            cp_async16(sB + so, b + (size_t)r * K + c16 * 4);
        }
        asm volatile("cp.async.commit_group;" ::: "memory");
    };

    load_stage(0, 0);
    load_stage(1, 1);

    for (int c = 0; c < nch; c++) {
        int slot = c % NST;
        asm volatile("cp.async.wait_group 1;" ::: "memory");
        __syncthreads();
        if (c + 2 < nch) load_stage(c + 2, (c + 2) % NST);

        const float* As = sm + slot * STAGE_F;
        const float* Bs = As + A_F;

#pragma unroll
        for (int ks = 0; ks < 4; ks++) {
            const int kk = ks * 8;
            uint32_t af[4][4], bf[8][2];
#pragma unroll
            for (int mt = 0; mt < 4; mt++) {
                const float* p = As + (wm * 64 + mt * 16 + g) * SROW + kk + t;
                af[mt][0] = cvt_tf32(p[0]);
                af[mt][1] = cvt_tf32(p[8 * SROW]);
                af[mt][2] = cvt_tf32(p[4]);
                af[mt][3] = cvt_tf32(p[8 * SROW + 4]);
            }
#pragma unroll
            for (int nt = 0; nt < 8; nt++) {
                const float* p = Bs + (wn * 64 + nt * 8 + g) * SROW + kk + t;
                bf[nt][0] = __float_as_uint(p[0]);
                bf[nt][1] = __float_as_uint(p[4]);
            }
#pragma unroll
            for (int mt = 0; mt < 4; mt++)
#pragma unroll
                for (int nt = 0; nt < 8; nt++)
                    mma_tf32(acc[mt][nt], af[mt], bf[nt]);
        }
    }

    // epilogue: +bias (+ReLU), float2 stores
#pragma unroll
    for (int mt = 0; mt < 4; mt++) {
        size_t row0 = m0 + wm * 64 + mt * 16 + g;
#pragma unroll
        for (int nt = 0; nt < 8; nt++) {
            int col = (int)n0 + wn * 64 + nt * 8 + t * 2;
            float b0 = bias[col], b1 = bias[col + 1];
            float v0 = acc[mt][nt][0] + b0;
            float v1 = acc[mt][nt][1] + b1;
            float v2 = acc[mt][nt][2] + b0;
            float v3 = acc[mt][nt][3] + b1;
            if (RELU) {
                v0 = fmaxf(v0, 0.f); v1 = fmaxf(v1, 0.f);
                v2 = fmaxf(v2, 0.f); v3 = fmaxf(v3, 0.f);
            }
            *(float2*)(C + row0 * (size_t)N + col)       = make_float2(v0, v1);
            *(float2*)(C + (row0 + 8) * (size_t)N + col) = make_float2(v2, v3);
        }
    }
}

// ---------------- window-3 local attention ----------------
__global__ void attn_kernel(const float* __restrict__ q,
                            const float* __restrict__ k,
                            const float* __restrict__ v,
                            const unsigned char* __restrict__ mask,
                            float* __restrict__ ctx) {
    int gw   = (int)((blockIdx.x * (size_t)blockDim.x + threadIdx.x) >> 5);
    int lane = threadIdx.x & 31;
    if (gw >= Mc * Hc) return;

    int h  = gw & (Hc - 1);
    int bl = gw >> 4;
    int l  = bl & (Lc - 1);
    int b  = bl >> 12;

    const float* qp = q + (size_t)bl * Dc + h * DHc;
    float q0 = qp[lane], q1 = qp[lane + 32];

    float s[3];
#pragma unroll
    for (int w = 0; w < 3; w++) {
        int idx    = l - 1 + w;
        bool valid = (idx >= 0) && (idx < Lc);
        int idxc   = min(max(idx, 0), Lc - 1);
        const float* kp = k + ((size_t)(b * Lc + idxc)) * Dc + h * DHc;
        float p = q0 * kp[lane] + q1 * kp[lane + 32];
#pragma unroll
        for (int off = 16; off > 0; off >>= 1)
            p += __shfl_xor_sync(0xffffffffu, p, off);
        bool ok = valid && (mask[b * Lc + idxc] == 0);
        s[w] = ok ? p * 0.125f : -1e30f;
    }

    float m  = fmaxf(s[0], fmaxf(s[1], s[2]));
    float e0 = expf(s[0] - m), e1 = expf(s[1] - m), e2 = expf(s[2] - m);
    float inv = 1.0f / (e0 + e1 + e2);
    float a0 = e0 * inv, a1 = e1 * inv, a2 = e2 * inv;

    int i0 = max(l - 1, 0), i2 = min(l + 1, Lc - 1);
    const float* v0 = v + ((size_t)(b * Lc + i0)) * Dc + h * DHc;
    const float* v1 = v + ((size_t)(b * Lc + l )) * Dc + h * DHc;
    const float* v2 = v + ((size_t)(b * Lc + i2)) * Dc + h * DHc;

    float o0 = a0 * v0[lane]      + a1 * v1[lane]      + a2 * v2[lane];
    float o1 = a0 * v0[lane + 32] + a1 * v1[lane + 32] + a2 * v2[lane + 32];

    float* cp = ctx + (size_t)bl * Dc + h * DHc;
    cp[lane]      = o0;
    cp[lane + 32] = o1;
}

// ---------------- out = LayerNorm(a + b) * gamma + beta ----------------
__device__ __forceinline__ float block_reduce_sum(float val, float* red) {
    int lane = threadIdx.x & 31, warp = threadIdx.x >> 5;
#pragma unroll
    for (int o = 16; o > 0; o >>= 1) val += __shfl_xor_sync(0xffffffffu, val, o);
    if (lane == 0) red[warp] = val;
    __syncthreads();
    if (warp == 0) {
        float t = (lane < 8) ? red[lane] : 0.f;
#pragma unroll
        for (int o = 4; o > 0; o >>= 1) t += __shfl_xor_sync(0xffffffffu, t, o);
        if (lane == 0) red[0] = t;
    }
    __syncthreads();
    float r = red[0];
    __syncthreads();
    return r;
}

__global__ void add_ln_kernel(const float* __restrict__ a,
                              const float* __restrict__ b,
                              const float* __restrict__ gamma,
                              const float* __restrict__ beta,
                              float* __restrict__ out) {
    __shared__ float red[32];
    const size_t row = blockIdx.x;
    const int tid = threadIdx.x;

    float4 x = ((const float4*)(a + row * Dc))[tid];
    float4 y = ((const float4*)(b + row * Dc))[tid];
    float v0 = x.x + y.x, v1 = x.y + y.y, v2 = x.z + y.z, v3 = x.w + y.w;

    float mean = block_reduce_sum(v0 + v1 + v2 + v3, red) * (1.0f / Dc);
    float d0 = v0 - mean, d1 = v1 - mean, d2 = v2 - mean, d3 = v3 - mean;
    float var = block_reduce_sum(d0 * d0 + d1 * d1 + d2 * d2 + d3 * d3, red) *
                (1.0f / Dc);
    float rstd = rsqrtf(var + 1e-5f);

    float4 g = ((const float4*)gamma)[tid];
    float4 be = ((const float4*)beta)[tid];
    float4 o;
    o.x = d0 * rstd * g.x + be.x;
    o.y = d1 * rstd * g.y + be.y;
    o.z = d2 * rstd * g.z + be.z;
    o.w = d3 * rstd * g.w + be.w;
    ((float4*)(out + row * Dc))[tid] = o;
}

// ---------------- launch ----------------
extern "C" void kernel_launch(void* const* d_in, const int* in_sizes, int n_in,
                              void* d_out, int out_size) {
    (void)in_sizes; (void)n_in; (void)out_size;
    const float*         X    = (const float*)d_in[0];
    const unsigned char* mask = (const unsigned char*)d_in[1];
    const float* pe  = (const float*)d_in[2];
    const float* Wq  = (const float*)d_in[3];
    const float* Wk  = (const float*)d_in[4];
    const float* Wv  = (const float*)d_in[5];
    const float* bq  = (const float*)d_in[6];
    const float* bk  = (const float*)d_in[7];
    const float* bv  = (const float*)d_in[8];
    const float* Wo  = (const float*)d_in[9];
    const float* bo  = (const float*)d_in[10];
    const float* g1  = (const float*)d_in[11];
    const float* be1 = (const float*)d_in[12];
    const float* W1  = (const float*)d_in[13];
    const float* b1  = (const float*)d_in[14];
    const float* W2  = (const float*)d_in[15];
    const float* b2  = (const float*)d_in[16];
    const float* g2  = (const float*)d_in[17];
    const float* be2 = (const float*)d_in[18];
    float* out = (float*)d_out;

    float *xpe, *q, *k, *v, *ctx, *x1, *hbuf;
    float *wqT, *wkT, *wvT, *woT, *w1T, *w2T;
    cudaGetSymbolAddress((void**)&xpe,  g_xpe);
    cudaGetSymbolAddress((void**)&q,    g_q);
    cudaGetSymbolAddress((void**)&k,    g_k);
    cudaGetSymbolAddress((void**)&v,    g_v);
    cudaGetSymbolAddress((void**)&ctx,  g_ctx);
    cudaGetSymbolAddress((void**)&x1,   g_x1);
    cudaGetSymbolAddress((void**)&hbuf, g_h);
    cudaGetSymbolAddress((void**)&wqT,  g_wqT);
    cudaGetSymbolAddress((void**)&wkT,  g_wkT);
    cudaGetSymbolAddress((void**)&wvT,  g_wvT);
    cudaGetSymbolAddress((void**)&woT,  g_woT);
    cudaGetSymbolAddress((void**)&w1T,  g_w1T);
    cudaGetSymbolAddress((void**)&w2T,  g_w2T);

    cudaFuncSetAttribute(mma_gemm_kernel<false>,
                         cudaFuncAttributeMaxDynamicSharedMemorySize, GEMM_SMEM);
    cudaFuncSetAttribute(mma_gemm_kernel<true>,
                         cudaFuncAttributeMaxDynamicSharedMemorySize, GEMM_SMEM);

    // 0. transpose + tf32-round weights ([N,K] row-major)
    dim3 tb(32, 8);
    transpose_kernel<<<dim3(Dc / 32, Dc / 32), tb>>>(Wq, wqT, Dc, Dc);
    transpose_kernel<<<dim3(Dc / 32, Dc / 32), tb>>>(Wk, wkT, Dc, Dc);
    transpose_kernel<<<dim3(Dc / 32, Dc / 32), tb>>>(Wv, wvT, Dc, Dc);
    transpose_kernel<<<dim3(Dc / 32, Dc / 32), tb>>>(Wo, woT, Dc, Dc);
    transpose_kernel<<<dim3(FFDc / 32, Dc / 32), tb>>>(W1, w1T, Dc, FFDc);
    transpose_kernel<<<dim3(Dc / 32, FFDc / 32), tb>>>(W2, w2T, FFDc, Dc);

    // 1. X + pe
    add_pe_kernel<<<(Mc * Dc / 4 + 255) / 256, 256>>>(X, pe, xpe);

    // 2. QKV projections (tensor cores, tf32 mma.sync)
    dim3 gD(Dc / 128, Mc / 256);      // (8, 128)
    mma_gemm_kernel<false><<<gD, 256, GEMM_SMEM>>>(xpe, wqT, bq, q, Dc, Dc);
    mma_gemm_kernel<false><<<gD, 256, GEMM_SMEM>>>(xpe, wkT, bk, k, Dc, Dc);
    mma_gemm_kernel<false><<<gD, 256, GEMM_SMEM>>>(xpe, wvT, bv, v, Dc, Dc);

    // 3. window-3 attention
    attn_kernel<<<(Mc * Hc) / 8, 256>>>(q, k, v, mask, ctx);

    // 4. output projection (reuse q as tmp)
    mma_gemm_kernel<false><<<gD, 256, GEMM_SMEM>>>(ctx, woT, bo, q, Dc, Dc);

    // 5. LN1(xpe + attn_proj)
    add_ln_kernel<<<Mc, 256>>>(xpe, q, g1, be1, x1);

    // 6. FFN
    dim3 gF(FFDc / 128, Mc / 256);    // (32, 128)
    mma_gemm_kernel<true ><<<gF, 256, GEMM_SMEM>>>(x1, w1T, b1, hbuf, FFDc, Dc);
    mma_gemm_kernel<false><<<gD, 256, GEMM_SMEM>>>(hbuf, w2T, b2, k /*tmp*/, Dc, FFDc);

    // 7. LN2(x1 + ffn) -> output
    add_ln_kernel<<<Mc, 256>>>(x1, k, g2, be2, out);
}

// round 10
// speedup vs baseline: 3.5365x; 1.0232x over previous
#include <cuda_runtime.h>
#include <math.h>
#include <stdint.h>

// ---------------- problem constants ----------------
#define Bc   8
#define Lc   4096
#define Dc   1024
#define Hc   16
#define DHc  64
#define Mc   (Bc * Lc)      // 32768 rows
#define FFDc 4096           // FF * D

// ---------------- device scratch (static, allocation-guard safe) ----------------
__device__ float g_xpe [(size_t)Mc * Dc];   // X + pe (residual 0, full precision)
__device__ float g_xper[(size_t)Mc * Dc];   // X + pe, tf32-rounded (GEMM A)
__device__ float g_q   [(size_t)Mc * Dc];   // q, later reused as attn@Wo tmp
__device__ float g_k   [(size_t)Mc * Dc];   // k, later reused as ffn out tmp
__device__ float g_v   [(size_t)Mc * Dc];   // v
__device__ float g_ctx [(size_t)Mc * Dc];   // attention context (tf32-rounded)
__device__ float g_x1  [(size_t)Mc * Dc];   // after LN1 (residual 1, full)
__device__ float g_x1r [(size_t)Mc * Dc];   // after LN1, tf32-rounded (GEMM A)
__device__ float g_h   [(size_t)Mc * FFDc]; // FFN hidden (tf32-rounded by epilogue)
// transposed + tf32-rounded weights ([N, K] row-major)
__device__ float g_wqT[(size_t)Dc * Dc];
__device__ float g_wkT[(size_t)Dc * Dc];
__device__ float g_wvT[(size_t)Dc * Dc];
__device__ float g_woT[(size_t)Dc * Dc];
__device__ float g_w1T[(size_t)Dc * FFDc];
__device__ float g_w2T[(size_t)FFDc * Dc];

// ---------------- small PTX helpers ----------------
__device__ __forceinline__ uint32_t cvt_tf32(float x) {
    uint32_t r;
    asm("cvt.rna.tf32.f32 %0, %1;" : "=r"(r) : "f"(x));
    return r;
}
__device__ __forceinline__ float round_tf32(float x) {
    return __uint_as_float(cvt_tf32(x));
}

__device__ __forceinline__ uint32_t smem_u32(const void* p) {
    uint32_t a;
    asm("{ .reg .u64 t; cvta.to.shared.u64 t, %1; cvt.u32.u64 %0, t; }"
        : "=r"(a) : "l"(p));
    return a;
}

__device__ __forceinline__ void cp_async16(uint32_t dst, const void* src) {
    asm volatile("cp.async.cg.shared.global [%0], [%1], 16;"
                 :: "r"(dst), "l"(src));
}

__device__ __forceinline__ void mma_tf32(float* c, const uint32_t* a,
                                         const uint32_t* b) {
    asm volatile(
        "mma.sync.aligned.m16n8k8.row.col.f32.tf32.tf32.f32 "
        "{%0,%1,%2,%3}, {%4,%5,%6,%7}, {%8,%9}, {%0,%1,%2,%3};"
        : "+f"(c[0]), "+f"(c[1]), "+f"(c[2]), "+f"(c[3])
        : "r"(a[0]), "r"(a[1]), "r"(a[2]), "r"(a[3]),
          "r"(b[0]), "r"(b[1]));
}

// ---------------- kernel 1: X + pe (dual output: full + tf32) ----------------
__global__ void add_pe_kernel(const float* __restrict__ X,
                              const float* __restrict__ pe,
                              float* __restrict__ out,
                              float* __restrict__ out_r) {
    size_t i = (size_t)blockIdx.x * blockDim.x + threadIdx.x;
    const size_t n4 = (size_t)Mc * Dc / 4;
    if (i >= n4) return;
    const size_t per = (size_t)Lc * Dc / 4;
    float4 x = ((const float4*)X)[i];
    float4 p = ((const float4*)pe)[i % per];
    float4 o;
    o.x = x.x + p.x; o.y = x.y + p.y; o.z = x.z + p.z; o.w = x.w + p.w;
    ((float4*)out)[i] = o;
    float4 r;
    r.x = round_tf32(o.x); r.y = round_tf32(o.y);
    r.z = round_tf32(o.z); r.w = round_tf32(o.w);
    ((float4*)out_r)[i] = r;
}

// ---------------- transpose + tf32-round: out[C,R] = rna(in[R,C]^T) ----------
__global__ void transpose_kernel(const float* __restrict__ in,
                                 float* __restrict__ out, int R, int C) {
    __shared__ float t[32][33];
    int bx = blockIdx.x * 32;
    int by = blockIdx.y * 32;
    int x = threadIdx.x, y = threadIdx.y;  // 32 x 8
#pragma unroll
    for (int i = 0; i < 32; i += 8)
        t[y + i][x] = in[(size_t)(by + y + i) * C + bx + x];
    __syncthreads();
#pragma unroll
    for (int i = 0; i < 32; i += 8)
        out[(size_t)(bx + y + i) * R + by + x] = round_tf32(t[x][y + i]);
}

// ============================================================================
// tf32 mma.sync GEMM:  C[M,N] = A[M,K] @ Wt[N,K]^T + bias  (opt ReLU / round)
// 256x128 tile, BK=32, 3-stage cp.async pipeline, 8 warps (4x2), 64x64/warp.
// A and Wt are PRE-ROUNDED to tf32 in gmem -> no cvt in the mainloop.
// smem row stride = 36 floats: conflict-free fragment LDS + 16B cp.async align.
// ============================================================================
#define BKt      32
#define SROW     36
#define A_F      (256 * SROW)          // floats in A tile
#define B_F      (128 * SROW)          // floats in B tile
#define STAGE_F  (A_F + B_F)
#define NST      3
#define GEMM_SMEM (NST * STAGE_F * 4)  // 165888 bytes

template <bool RELU, bool ROUND>
__global__ __launch_bounds__(256, 1)
void mma_gemm_kernel(const float* __restrict__ A,
                     const float* __restrict__ Wt,   // [N, K] row-major, tf32
                     const float* __restrict__ bias,
                     float* __restrict__ C,
                     int N, int K) {
    extern __shared__ float sm[];
    const int tid  = threadIdx.x;
    const int wid  = tid >> 5, lane = tid & 31;
    const int g    = lane >> 2, t = lane & 3;
    const int wm   = wid >> 1, wn = wid & 1;       // 4 x 2 warp grid
    const size_t m0 = (size_t)blockIdx.y * 256;
    const size_t n0 = (size_t)blockIdx.x * 128;
    const float* gA = A  + m0 * (size_t)K;
    const float* gB = Wt + n0 * (size_t)K;
    const uint32_t sbase = smem_u32(sm);

    float acc[4][8][4];
#pragma unroll
    for (int i = 0; i < 4; i++)
#pragma unroll
        for (int j = 0; j < 8; j++)
#pragma unroll
            for (int r = 0; r < 4; r++) acc[i][j][r] = 0.f;

    const int nch = K / BKt;

    auto load_stage = [&](int c, int slot) {
        uint32_t sA = sbase + (uint32_t)slot * STAGE_F * 4;
        uint32_t sB = sA + A_F * 4;
        const float* a = gA + (size_t)c * BKt;
        const float* b = gB + (size_t)c * BKt;
#pragma unroll
        for (int qq = 0; qq < 8; qq++) {      // A: 256 rows x 8 chunks
            int id = qq * 256 + tid;
            int r = id >> 3, c16 = id & 7;
            uint32_t so = (uint32_t)(r * SROW + c16 * 4) * 4;
            cp_async16(sA + so, a + (size_t)r * K + c16 * 4);
        }
#pragma unroll
        for (int qq = 0; qq < 4; qq++) {      // B: 128 rows x 8 chunks
            int id = qq * 256 + tid;
            int r = id >> 3, c16 = id & 7;
            uint32_t so = (uint32_t)(r * SROW + c16 * 4) * 4;
            cp_async16(sB + so, b + (size_t)r * K + c16 * 4);
        }
        asm volatile("cp.async.commit_group;" ::: "memory");
    };

    load_stage(0, 0);
    load_stage(1, 1);

    for (int c = 0; c < nch; c++) {
        int slot = c % NST;
        asm volatile("cp.async.wait_group 1;" ::: "memory");
        __syncthreads();
        if (c + 2 < nch) load_stage(c + 2, (c + 2) % NST);

        const float* As = sm + slot * STAGE_F;
        const float* Bs = As + A_F;

#pragma unroll
        for (int ks = 0; ks < 4; ks++) {
            const int kk = ks * 8;
            uint32_t af[4][4], bf[8][2];
#pragma unroll
            for (int mt = 0; mt < 4; mt++) {
                const float* p = As + (wm * 64 + mt * 16 + g) * SROW + kk + t;
                af[mt][0] = __float_as_uint(p[0]);
                af[mt][1] = __float_as_uint(p[8 * SROW]);
                af[mt][2] = __float_as_uint(p[4]);
                af[mt][3] = __float_as_uint(p[8 * SROW + 4]);
            }
#pragma unroll
            for (int nt = 0; nt < 8; nt++) {
                const float* p = Bs + (wn * 64 + nt * 8 + g) * SROW + kk + t;
                bf[nt][0] = __float_as_uint(p[0]);
                bf[nt][1] = __float_as_uint(p[4]);
            }
#pragma unroll
            for (int mt = 0; mt < 4; mt++)
#pragma unroll
                for (int nt = 0; nt < 8; nt++)
                    mma_tf32(acc[mt][nt], af[mt], bf[nt]);
        }
    }

    // epilogue: +bias (+ReLU) (+tf32 round), float2 stores
#pragma unroll
    for (int mt = 0; mt < 4; mt++) {
        size_t row0 = m0 + wm * 64 + mt * 16 + g;
#pragma unroll
        for (int nt = 0; nt < 8; nt++) {
            int col = (int)n0 + wn * 64 + nt * 8 + t * 2;
            float b0 = bias[col], b1 = bias[col + 1];
            float v0 = acc[mt][nt][0] + b0;
            float v1 = acc[mt][nt][1] + b1;
            float v2 = acc[mt][nt][2] + b0;
            float v3 = acc[mt][nt][3] + b1;
            if (RELU) {
                v0 = fmaxf(v0, 0.f); v1 = fmaxf(v1, 0.f);
                v2 = fmaxf(v2, 0.f); v3 = fmaxf(v3, 0.f);
            }
            if (ROUND) {
                v0 = round_tf32(v0); v1 = round_tf32(v1);
                v2 = round_tf32(v2); v3 = round_tf32(v3);
            }
            *(float2*)(C + row0 * (size_t)N + col)       = make_float2(v0, v1);
            *(float2*)(C + (row0 + 8) * (size_t)N + col) = make_float2(v2, v3);
        }
    }
}

// ---------------- window-3 local attention (tf32-rounded output) ------------
__global__ void attn_kernel(const float* __restrict__ q,
                            const float* __restrict__ k,
                            const float* __restrict__ v,
                            const unsigned char* __restrict__ mask,
                            float* __restrict__ ctx) {
    int gw   = (int)((blockIdx.x * (size_t)blockDim.x + threadIdx.x) >> 5);
    int lane = threadIdx.x & 31;
    if (gw >= Mc * Hc) return;

    int h  = gw & (Hc - 1);
    int bl = gw >> 4;
    int l  = bl & (Lc - 1);
    int b  = bl >> 12;

    const float* qp = q + (size_t)bl * Dc + h * DHc;
    float q0 = qp[lane], q1 = qp[lane + 32];

    float s[3];
#pragma unroll
    for (int w = 0; w < 3; w++) {
        int idx    = l - 1 + w;
        bool valid = (idx >= 0) && (idx < Lc);
        int idxc   = min(max(idx, 0), Lc - 1);
        const float* kp = k + ((size_t)(b * Lc + idxc)) * Dc + h * DHc;
        float p = q0 * kp[lane] + q1 * kp[lane + 32];
#pragma unroll
        for (int off = 16; off > 0; off >>= 1)
            p += __shfl_xor_sync(0xffffffffu, p, off);
        bool ok = valid && (mask[b * Lc + idxc] == 0);
        s[w] = ok ? p * 0.125f : -1e30f;
    }

    float m  = fmaxf(s[0], fmaxf(s[1], s[2]));
    float e0 = expf(s[0] - m), e1 = expf(s[1] - m), e2 = expf(s[2] - m);
    float inv = 1.0f / (e0 + e1 + e2);
    float a0 = e0 * inv, a1 = e1 * inv, a2 = e2 * inv;

    int i0 = max(l - 1, 0), i2 = min(l + 1, Lc - 1);
    const float* v0 = v + ((size_t)(b * Lc + i0)) * Dc + h * DHc;
    const float* v1 = v + ((size_t)(b * Lc + l )) * Dc + h * DHc;
    const float* v2 = v + ((size_t)(b * Lc + i2)) * Dc + h * DHc;

    float o0 = a0 * v0[lane]      + a1 * v1[lane]      + a2 * v2[lane];
    float o1 = a0 * v0[lane + 32] + a1 * v1[lane + 32] + a2 * v2[lane + 32];

    float* cp = ctx + (size_t)bl * Dc + h * DHc;
    cp[lane]      = round_tf32(o0);   // ctx only feeds the Wo GEMM
    cp[lane + 32] = round_tf32(o1);
}

// ---------------- out = LayerNorm(a + b) * gamma + beta ----------------
__device__ __forceinline__ float block_reduce_sum(float val, float* red) {
    int lane = threadIdx.x & 31, warp = threadIdx.x >> 5;
#pragma unroll
    for (int o = 16; o > 0; o >>= 1) val += __shfl_xor_sync(0xffffffffu, val, o);
    if (lane == 0) red[warp] = val;
    __syncthreads();
    if (warp == 0) {
        float t = (lane < 8) ? red[lane] : 0.f;
#pragma unroll
        for (int o = 4; o > 0; o >>= 1) t += __shfl_xor_sync(0xffffffffu, t, o);
        if (lane == 0) red[0] = t;
    }
    __syncthreads();
    float r = red[0];
    __syncthreads();
    return r;
}

template <bool DUAL>
__global__ void add_ln_kernel(const float* __restrict__ a,
                              const float* __restrict__ b,
                              const float* __restrict__ gamma,
                              const float* __restrict__ beta,
                              float* __restrict__ out,
                              float* __restrict__ out_r) {
    __shared__ float red[32];
    const size_t row = blockIdx.x;
    const int tid = threadIdx.x;

    float4 x = ((const float4*)(a + row * Dc))[tid];
    float4 y = ((const float4*)(b + row * Dc))[tid];
    float v0 = x.x + y.x, v1 = x.y + y.y, v2 = x.z + y.z, v3 = x.w + y.w;

    float mean = block_reduce_sum(v0 + v1 + v2 + v3, red) * (1.0f / Dc);
    float d0 = v0 - mean, d1 = v1 - mean, d2 = v2 - mean, d3 = v3 - mean;
    float var = block_reduce_sum(d0 * d0 + d1 * d1 + d2 * d2 + d3 * d3, red) *
                (1.0f / Dc);
    float rstd = rsqrtf(var + 1e-5f);

    float4 g = ((const float4*)gamma)[tid];
    float4 be = ((const float4*)beta)[tid];
    float4 o;
    o.x = d0 * rstd * g.x + be.x;
    o.y = d1 * rstd * g.y + be.y;
    o.z = d2 * rstd * g.z + be.z;
    o.w = d3 * rstd * g.w + be.w;
    ((float4*)(out + row * Dc))[tid] = o;
    if (DUAL) {
        float4 r;
        r.x = round_tf32(o.x); r.y = round_tf32(o.y);
        r.z = round_tf32(o.z); r.w = round_tf32(o.w);
        ((float4*)(out_r + row * Dc))[tid] = r;
    }
}

// ---------------- launch ----------------
extern "C" void kernel_launch(void* const* d_in, const int* in_sizes, int n_in,
                              void* d_out, int out_size) {
    (void)in_sizes; (void)n_in; (void)out_size;
    const float*         X    = (const float*)d_in[0];
    const unsigned char* mask = (const unsigned char*)d_in[1];
    const float* pe  = (const float*)d_in[2];
    const float* Wq  = (const float*)d_in[3];
    const float* Wk  = (const float*)d_in[4];
    const float* Wv  = (const float*)d_in[5];
    const float* bq  = (const float*)d_in[6];
    const float* bk  = (const float*)d_in[7];
    const float* bv  = (const float*)d_in[8];
    const float* Wo  = (const float*)d_in[9];
    const float* bo  = (const float*)d_in[10];
    const float* g1  = (const float*)d_in[11];
    const float* be1 = (const float*)d_in[12];
    const float* W1  = (const float*)d_in[13];
    const float* b1  = (const float*)d_in[14];
    const float* W2  = (const float*)d_in[15];
    const float* b2  = (const float*)d_in[16];
    const float* g2  = (const float*)d_in[17];
    const float* be2 = (const float*)d_in[18];
    float* out = (float*)d_out;

    float *xpe, *xper, *q, *k, *v, *ctx, *x1, *x1r, *hbuf;
    float *wqT, *wkT, *wvT, *woT, *w1T, *w2T;
    cudaGetSymbolAddress((void**)&xpe,  g_xpe);
    cudaGetSymbolAddress((void**)&xper, g_xper);
    cudaGetSymbolAddress((void**)&q,    g_q);
    cudaGetSymbolAddress((void**)&k,    g_k);
    cudaGetSymbolAddress((void**)&v,    g_v);
    cudaGetSymbolAddress((void**)&ctx,  g_ctx);
    cudaGetSymbolAddress((void**)&x1,   g_x1);
    cudaGetSymbolAddress((void**)&x1r,  g_x1r);
    cudaGetSymbolAddress((void**)&hbuf, g_h);
    cudaGetSymbolAddress((void**)&wqT,  g_wqT);
    cudaGetSymbolAddress((void**)&wkT,  g_wkT);
    cudaGetSymbolAddress((void**)&wvT,  g_wvT);
    cudaGetSymbolAddress((void**)&woT,  g_woT);
    cudaGetSymbolAddress((void**)&w1T,  g_w1T);
    cudaGetSymbolAddress((void**)&w2T,  g_w2T);

    cudaFuncSetAttribute(mma_gemm_kernel<false, false>,
                         cudaFuncAttributeMaxDynamicSharedMemorySize, GEMM_SMEM);
    cudaFuncSetAttribute(mma_gemm_kernel<true, true>,
                         cudaFuncAttributeMaxDynamicSharedMemorySize, GEMM_SMEM);

    dim3 tb(32, 8);
    dim3 gD(Dc / 128, Mc / 256);      // (8, 128)
    dim3 gF(FFDc / 128, Mc / 256);    // (32, 128)

    // launches 0-2: QKV weight transposes
    transpose_kernel<<<dim3(Dc / 32, Dc / 32), tb>>>(Wq, wqT, Dc, Dc);
    transpose_kernel<<<dim3(Dc / 32, Dc / 32), tb>>>(Wk, wkT, Dc, Dc);
    transpose_kernel<<<dim3(Dc / 32, Dc / 32), tb>>>(Wv, wvT, Dc, Dc);
    // launch 3: X + pe (full + rounded)
    add_pe_kernel<<<(Mc * Dc / 4 + 255) / 256, 256>>>(X, pe, xpe, xper);
    // launches 4-6: QKV GEMMs (launch 5 = gemm_k lands in the ncu -s 5 window)
    mma_gemm_kernel<false, false><<<gD, 256, GEMM_SMEM>>>(xper, wqT, bq, q, Dc, Dc);
    mma_gemm_kernel<false, false><<<gD, 256, GEMM_SMEM>>>(xper, wkT, bk, k, Dc, Dc);
    mma_gemm_kernel<false, false><<<gD, 256, GEMM_SMEM>>>(xper, wvT, bv, v, Dc, Dc);
    // launch 7: Wo transpose; launch 8: attention (rounded ctx)
    transpose_kernel<<<dim3(Dc / 32, Dc / 32), tb>>>(Wo, woT, Dc, Dc);
    attn_kernel<<<(Mc * Hc) / 8, 256>>>(q, k, v, mask, ctx);
    // launch 9: output projection (reuse q as tmp)
    mma_gemm_kernel<false, false><<<gD, 256, GEMM_SMEM>>>(ctx, woT, bo, q, Dc, Dc);
    // launches 10-11: FFN weight transposes
    transpose_kernel<<<dim3(FFDc / 32, Dc / 32), tb>>>(W1, w1T, Dc, FFDc);
    transpose_kernel<<<dim3(Dc / 32, FFDc / 32), tb>>>(W2, w2T, FFDc, Dc);
    // launch 12: LN1(xpe + attn_proj) -> x1 (full) + x1r (rounded)
    add_ln_kernel<true><<<Mc, 256>>>(xpe, q, g1, be1, x1, x1r);
    // launches 13-14: FFN (FFN1 epilogue rounds hbuf for FFN2's A-feed)
    mma_gemm_kernel<true,  true ><<<gF, 256, GEMM_SMEM>>>(x1r, w1T, b1, hbuf, FFDc, Dc);
    mma_gemm_kernel<false, false><<<gD, 256, GEMM_SMEM>>>(hbuf, w2T, b2, k /*tmp*/, Dc, FFDc);
    // launch 15: LN2(x1 + ffn) -> output
    add_ln_kernel<false><<<Mc, 256>>>(x1, k, g2, be2, out, nullptr);
}